// round 13
// baseline (speedup 1.0000x reference)
#include <cuda_runtime.h>
#include <cuda_bf16.h>
#include <cuda_fp16.h>
#include <math_constants.h>
#include <cstdint>

// Problem constants
#define D_MODEL 512
#define NHEADS  8
#define DK      64
#define BATCH   2
#define SEQ     2048
#define MTOK    (BATCH * SEQ)   // 4096
#define NBH     (BATCH * NHEADS)
#define WSZ     (D_MODEL * D_MODEL)

#define LOG2E 1.44269504088896f

// ---------------------------------------------------------------------------
// Scratch (device globals) — all fp16
// ---------------------------------------------------------------------------
__device__ __half g_xf[MTOK * D_MODEL];       // x fp16
__device__ __half g_wf[4][WSZ];               // Wq,Wk,Wv,Wo transposed fp16
__device__ __half g_qf[NBH * SEQ * DK];       // Q fp16 (pre-scaled log2e/8)
__device__ __half g_kf[NBH * SEQ * DK];       // K fp16
__device__ __half g_vf[NBH * DK * SEQ];       // V^T fp16
__device__ __half g_cf[MTOK * D_MODEL];       // ctx fp16

// ---------------------------------------------------------------------------
// Helpers
// ---------------------------------------------------------------------------
__device__ __forceinline__ uint32_t smem_u32(const void* p) {
    uint32_t a;
    asm("{ .reg .u64 t; cvta.to.shared.u64 t, %1; cvt.u32.u64 %0, t; }"
        : "=r"(a) : "l"(p));
    return a;
}
__device__ __forceinline__ void cp16(uint32_t dst, const void* src) {
    asm volatile("cp.async.cg.shared.global [%0], [%1], 16;" :: "r"(dst), "l"(src));
}
__device__ __forceinline__ void mma16816h(float* c, const uint32_t* a, const uint32_t* b) {
    asm volatile("mma.sync.aligned.m16n8k16.row.col.f32.f16.f16.f32 "
        "{%0,%1,%2,%3}, {%4,%5,%6,%7}, {%8,%9}, {%0,%1,%2,%3};"
        : "+f"(c[0]), "+f"(c[1]), "+f"(c[2]), "+f"(c[3])
        : "r"(a[0]), "r"(a[1]), "r"(a[2]), "r"(a[3]), "r"(b[0]), "r"(b[1]));
}
__device__ __forceinline__ void ldsm_x4(uint32_t& r0, uint32_t& r1, uint32_t& r2,
                                        uint32_t& r3, uint32_t addr) {
    asm volatile("ldmatrix.sync.aligned.m8n8.x4.shared.b16 {%0,%1,%2,%3}, [%4];"
        : "=r"(r0), "=r"(r1), "=r"(r2), "=r"(r3) : "r"(addr));
}
__device__ __forceinline__ uint32_t ex2h2(uint32_t a) {
    uint32_t r;
    asm("ex2.approx.f16x2 %0, %1;" : "=r"(r) : "r"(a));
    return r;
}
__device__ __forceinline__ uint32_t packh2(float x, float y) {
    __half2 t = __floats2half2_rn(x, y);
    return *(uint32_t*)&t;
}

// ---------------------------------------------------------------------------
// Prep: weights transpose->fp16 (z<4) + x->fp16 (z>=4), one launch.
// ---------------------------------------------------------------------------
struct W4 { const float* w[4]; };

__global__ __launch_bounds__(256)
void prep_kernel(W4 ws, const float* __restrict__ x,
                 __half* __restrict__ wf, __half* __restrict__ xf)
{
    const int z = blockIdx.z;
    if (z < 4) {
        __shared__ float t[32][33];
        const float* W = ws.w[z];
        __half* dst = wf + (size_t)z * WSZ;
        const int k0 = blockIdx.x * 32, n0 = blockIdx.y * 32;
#pragma unroll
        for (int r = threadIdx.y; r < 32; r += 8)
            t[r][threadIdx.x] = W[(size_t)(k0 + r) * D_MODEL + n0 + threadIdx.x];
        __syncthreads();
#pragma unroll
        for (int r = threadIdx.y; r < 32; r += 8) {
            float v = t[threadIdx.x][r];
            dst[(size_t)(n0 + r) * D_MODEL + k0 + threadIdx.x] = __float2half_rn(v);
        }
    } else {
        const int strip = z - 4;
        const int blk   = strip * 256 + blockIdx.y * 16 + blockIdx.x;
        const int i     = blk * 256 + threadIdx.y * 32 + threadIdx.x;
        float4 v = ((const float4*)x)[i];
        uint32_t* op = (uint32_t*)xf;
        op[2 * i + 0] = packh2(v.x, v.y);
        op[2 * i + 1] = packh2(v.z, v.w);
    }
}

// ---------------------------------------------------------------------------
// fp16 HMMA GEMM core, BKC=32, 4-stage cp.async pipeline (wait_group 2).
// 128x128 tile, 256 thr (8 warps 2x4), 2 CTAs/SM (160KB smem total).
// ---------------------------------------------------------------------------
#define HKC      32
#define HSTR     40
#define HTILE    (128 * HSTR)
#define HSTAGES  4
#define H_SMEM_BYTES (HSTAGES * 2 * HTILE * 2)   // 81920

__device__ __forceinline__ void load_tile32h(uint32_t sdst, const __half* src, int tid)
{
#pragma unroll
    for (int i = 0; i < 2; ++i) {
        const int idx = tid + i * 256;
        const int row = idx >> 2;
        const int c16 = idx & 3;
        cp16(sdst + row * (HSTR * 2) + c16 * 16,
             src + (size_t)row * D_MODEL + c16 * 8);
    }
}

__device__ __forceinline__ void gemm_mainloop_h(
    __half* sm, uint32_t smb,
    const __half* a0, const __half* bw,
    int tid, int lane, int wm, int wn, float c[4][4][4])
{
    auto sload = [&](int s, int ch) {
        const int kc = ch * HKC;
        const uint32_t sb = smb + (s * 2 * HTILE) * 2;
        load_tile32h(sb, a0 + kc, tid);
        load_tile32h(sb + HTILE * 2, bw + kc, tid);
        asm volatile("cp.async.commit_group;" ::: "memory");
    };

    const int NCHUNK = D_MODEL / HKC;  // 16
    sload(0, 0);
    sload(1, 1);
    sload(2, 2);
    const int kkb = (lane & 3) * 2;

    for (int ch = 0; ch < NCHUNK; ++ch) {
        asm volatile("cp.async.wait_group 2;" ::: "memory");
        __syncthreads();
        if (ch + 3 < NCHUNK) sload((ch + 3) & 3, ch + 3);
        else asm volatile("cp.async.commit_group;" ::: "memory");

        const int s = ch & 3;
        const __half* sA = sm + s * 2 * HTILE;
        const __half* sB = sA + HTILE;

#pragma unroll
        for (int k16 = 0; k16 < 2; ++k16) {
            const int kk = k16 * 16 + kkb;
            uint32_t bf[4][2];
#pragma unroll
            for (int ni = 0; ni < 4; ++ni) {
                const int rB = wn * 32 + ni * 8 + (lane >> 2);
                bf[ni][0] = *(const uint32_t*)&sB[rB * HSTR + kk];
                bf[ni][1] = *(const uint32_t*)&sB[rB * HSTR + kk + 8];
            }
#pragma unroll
            for (int mi = 0; mi < 4; ++mi) {
                const int rA = wm * 64 + mi * 16 + (lane >> 2);
                uint32_t a[4];
                a[0] = *(const uint32_t*)&sA[(rA    ) * HSTR + kk];
                a[1] = *(const uint32_t*)&sA[(rA + 8) * HSTR + kk];
                a[2] = *(const uint32_t*)&sA[(rA    ) * HSTR + kk + 8];
                a[3] = *(const uint32_t*)&sA[(rA + 8) * HSTR + kk + 8];
#pragma unroll
                for (int ni = 0; ni < 4; ++ni)
                    mma16816h(c[mi][ni], a, bf[ni]);
            }
        }
    }
    __syncthreads();
}

// ---------------------------------------------------------------------------
// Fused QKV projection (1-pass fp16)
// ---------------------------------------------------------------------------
__global__ __launch_bounds__(256, 2)
void gemm_qkv_kernel(const __half* __restrict__ Xf,
                     const __half* __restrict__ Wf,
                     const float* __restrict__ bq,
                     const float* __restrict__ bk,
                     const float* __restrict__ bv,
                     __half* __restrict__ qf,
                     __half* __restrict__ kf,
                     __half* __restrict__ vf)
{
    extern __shared__ __half smh[];
    const int tid  = threadIdx.x;
    const int wid  = tid >> 5;
    const int lane = tid & 31;
    const int wm   = wid >> 2;
    const int wn   = wid & 3;
    const int which = blockIdx.x >> 2;
    const int n0   = (blockIdx.x & 3) * 128;
    const int m0   = blockIdx.y * 128;

    const float* bias = (which == 0) ? bq : (which == 1) ? bk : bv;

    float c[4][4][4] = {};
    gemm_mainloop_h(smh, smem_u32(smh),
                    Xf + (size_t)m0 * D_MODEL,
                    Wf + (size_t)which * WSZ + (size_t)n0 * D_MODEL,
                    tid, lane, wm, wn, c);

    const float sc = (which == 0) ? (0.125f * LOG2E) : 1.0f;
#pragma unroll
    for (int mi = 0; mi < 4; ++mi) {
        const int row0 = m0 + wm * 64 + mi * 16 + (lane >> 2);
#pragma unroll
        for (int ni = 0; ni < 4; ++ni) {
            const int col = n0 + wn * 32 + ni * 8 + (lane & 3) * 2;
            const float b0 = bias[col], b1 = bias[col + 1];
#pragma unroll
            for (int half = 0; half < 2; ++half) {
                const int m = row0 + half * 8;
                const float vx = (c[mi][ni][half * 2 + 0] + b0) * sc;
                const float vy = (c[mi][ni][half * 2 + 1] + b1) * sc;
                const int b = m >> 11, sN = m & (SEQ - 1);
                const int h = col >> 6, d = col & (DK - 1);
                if (which != 2) {
                    __half* dst = (which == 0) ? qf : kf;
                    const size_t idx = ((size_t)(b * NHEADS + h) * SEQ + sN) * DK + d;
                    *(uint32_t*)&dst[idx] = packh2(vx, vy);
                } else {
                    const size_t idx = ((size_t)(b * NHEADS + h) * DK + d) * SEQ + sN;
                    vf[idx]       = __float2half_rn(vx);
                    vf[idx + SEQ] = __float2half_rn(vy);
                }
            }
        }
    }
}

// ---------------------------------------------------------------------------
// Output projection (1-pass fp16): fp32 out + bias
// ---------------------------------------------------------------------------
__global__ __launch_bounds__(256, 2)
void gemm_out_kernel(const __half* __restrict__ Cf,
                     const __half* __restrict__ Wo,
                     const float* __restrict__ bias,
                     float* __restrict__ outf)
{
    extern __shared__ __half smh[];
    const int tid  = threadIdx.x;
    const int wid  = tid >> 5;
    const int lane = tid & 31;
    const int wm   = wid >> 2;
    const int wn   = wid & 3;
    const int n0   = blockIdx.x * 128;
    const int m0   = blockIdx.y * 128;

    float c[4][4][4] = {};
    gemm_mainloop_h(smh, smem_u32(smh),
                    Cf + (size_t)m0 * D_MODEL,
                    Wo + (size_t)n0 * D_MODEL,
                    tid, lane, wm, wn, c);

#pragma unroll
    for (int mi = 0; mi < 4; ++mi) {
        const int row0 = m0 + wm * 64 + mi * 16 + (lane >> 2);
#pragma unroll
        for (int ni = 0; ni < 4; ++ni) {
            const int col = n0 + wn * 32 + ni * 8 + (lane & 3) * 2;
            const float b0 = bias[col], b1 = bias[col + 1];
#pragma unroll
            for (int half = 0; half < 2; ++half) {
                const int m = row0 + half * 8;
                float2 v;
                v.x = c[mi][ni][half * 2 + 0] + b0;
                v.y = c[mi][ni][half * 2 + 1] + b1;
                *(float2*)&outf[(size_t)m * D_MODEL + col] = v;
            }
        }
    }
}

// ---------------------------------------------------------------------------
// HMMA flash attention — fp16, ex2.f16x2 softmax fused in S-loop, l via
// ones-MMA. PAIRWISE j / n processing: 4 independent accumulator chains
// per MMA burst (2x the ILP of the serial version).
// CTA = 128 queries x one (b,h), 4 fat warps, 64-key tiles, 2 CTAs/SM.
// ---------------------------------------------------------------------------
#define KSTR   72
#define VSTR   72
#define KF_OFF 0
#define VF_OFF 4608
#define FSTG   9216
#define FL_SMEM_BYTES (2 * FSTG * 2)     // 36864 B
#define ONES_H2 0x3C003C00u

__global__ __launch_bounds__(128, 2)
void flash_hmma_kernel(const __half* __restrict__ qf,
                       const __half* __restrict__ kf,
                       const __half* __restrict__ vf,
                       __half* __restrict__ cf)
{
    extern __shared__ __half smh[];
    const int tid  = threadIdx.x;
    const int wid  = tid >> 5;
    const int lane = tid & 31;
    const int bh   = blockIdx.y;
    const int q0   = blockIdx.x * 128;
    const int kkb  = (lane & 3) * 2;
    const int qr   = lane >> 2;
    const int mrow = lane & 7;
    const int grp  = lane >> 3;

    const uint32_t smb = smem_u32(smh);
    const __half* qg = qf + ((size_t)bh * SEQ + q0) * DK;
    const __half* kg = kf + (size_t)bh * SEQ * DK;
    const __half* vg = vf + (size_t)bh * DK * SEQ;

    // ---- stage Q ----
#pragma unroll
    for (int i = 0; i < 8; ++i) {
        const int idx = tid + i * 128;
        const int row = idx >> 3;
        const int c16 = idx & 7;
        cp16(smb + (row * KSTR) * 2 + c16 * 16, qg + (size_t)row * DK + c16 * 8);
    }
    asm volatile("cp.async.commit_group;" ::: "memory");
    asm volatile("cp.async.wait_group 0;" ::: "memory");
    __syncthreads();

    uint32_t qfr[2][4][4];
#pragma unroll
    for (int mi = 0; mi < 2; ++mi) {
        const int rA = wid * 32 + mi * 16 + qr;
#pragma unroll
        for (int ks = 0; ks < 4; ++ks) {
            const int base = rA * KSTR + kkb + 16 * ks;
            qfr[mi][ks][0] = *(const uint32_t*)&smh[base];
            qfr[mi][ks][1] = *(const uint32_t*)&smh[base + 8 * KSTR];
            qfr[mi][ks][2] = *(const uint32_t*)&smh[base + 8];
            qfr[mi][ks][3] = *(const uint32_t*)&smh[base + 8 * KSTR + 8];
        }
    }
    __syncthreads();

    auto load_stage = [&](int st, int t) {
        const __half* ks = kg + (size_t)t * 64 * DK;
        const __half* vs = vg + (size_t)t * 64;
        const uint32_t sb = smb + st * FSTG * 2;
#pragma unroll
        for (int i = 0; i < 4; ++i) {
            const int idx = tid + i * 128;
            const int row = idx >> 3;
            const int c16 = idx & 7;
            cp16(sb + (KF_OFF + row * KSTR) * 2 + c16 * 16, ks + (size_t)row * DK + c16 * 8);
            cp16(sb + (VF_OFF + row * VSTR) * 2 + c16 * 16, vs + (size_t)row * SEQ + c16 * 8);
        }
        asm volatile("cp.async.commit_group;" ::: "memory");
    };

    float lrow[2][4] = {};
    float o[2][8][4] = {};
    const uint32_t onesf[2] = {ONES_H2, ONES_H2};

    const int NT = SEQ / 64;
    load_stage(0, 0);

    for (int t = 0; t < NT; ++t) {
        if (t + 1 < NT) {
            load_stage((t + 1) & 1, t + 1);
            asm volatile("cp.async.wait_group 1;" ::: "memory");
        } else {
            asm volatile("cp.async.wait_group 0;" ::: "memory");
        }
        __syncthreads();

        const uint32_t stg = smb + (t & 1) * FSTG * 2;

        // ---- S + softmax, PAIRWISE j (4 independent accumulator chains) ----
        uint32_t pf[2][4][4];
#pragma unroll
        for (int jp = 0; jp < 4; ++jp) {
            const int j0 = jp * 2, j1 = jp * 2 + 1;
            const uint32_t ka0 = stg + ((KF_OFF + (j0 * 8 + mrow) * KSTR + grp * 8) * 2);
            const uint32_t ka1 = stg + ((KF_OFF + (j1 * 8 + mrow) * KSTR + grp * 8) * 2);
            uint32_t kb0[4][2], kb1[4][2];
            ldsm_x4(kb0[0][0], kb0[0][1], kb0[1][0], kb0[1][1], ka0);
            ldsm_x4(kb0[2][0], kb0[2][1], kb0[3][0], kb0[3][1], ka0 + 64);
            ldsm_x4(kb1[0][0], kb1[0][1], kb1[1][0], kb1[1][1], ka1);
            ldsm_x4(kb1[2][0], kb1[2][1], kb1[3][0], kb1[3][1], ka1 + 64);

            float s00[4] = {}, s10[4] = {}, s01[4] = {}, s11[4] = {};
#pragma unroll
            for (int ks = 0; ks < 4; ++ks) {
                mma16816h(s00, qfr[0][ks], kb0[ks]);
                mma16816h(s10, qfr[1][ks], kb0[ks]);
                mma16816h(s01, qfr[0][ks], kb1[ks]);
                mma16816h(s11, qfr[1][ks], kb1[ks]);
            }
            pf[0][jp][0] = ex2h2(packh2(s00[0], s00[1]));
            pf[0][jp][1] = ex2h2(packh2(s00[2], s00[3]));
            pf[0][jp][2] = ex2h2(packh2(s01[0], s01[1]));
            pf[0][jp][3] = ex2h2(packh2(s01[2], s01[3]));
            pf[1][jp][0] = ex2h2(packh2(s10[0], s10[1]));
            pf[1][jp][1] = ex2h2(packh2(s10[2], s10[3]));
            pf[1][jp][2] = ex2h2(packh2(s11[0], s11[1]));
            pf[1][jp][3] = ex2h2(packh2(s11[2], s11[3]));
        }

        // ---- l += P @ ones (2 independent chains) ----
#pragma unroll
        for (int ks = 0; ks < 4; ++ks) {
            mma16816h(lrow[0], pf[0][ks], onesf);
            mma16816h(lrow[1], pf[1][ks], onesf);
        }

        // ---- O += P @ V, PAIRWISE n (4 independent chains) ----
#pragma unroll
        for (int np = 0; np < 4; ++np) {
            const int n0 = np * 2, n1 = np * 2 + 1;
            const uint32_t va0 = stg + ((VF_OFF + (n0 * 8 + mrow) * VSTR + grp * 8) * 2);
            const uint32_t va1 = stg + ((VF_OFF + (n1 * 8 + mrow) * VSTR + grp * 8) * 2);
            uint32_t vb0[4][2], vb1[4][2];
            ldsm_x4(vb0[0][0], vb0[0][1], vb0[1][0], vb0[1][1], va0);
            ldsm_x4(vb0[2][0], vb0[2][1], vb0[3][0], vb0[3][1], va0 + 64);
            ldsm_x4(vb1[0][0], vb1[0][1], vb1[1][0], vb1[1][1], va1);
            ldsm_x4(vb1[2][0], vb1[2][1], vb1[3][0], vb1[3][1], va1 + 64);
#pragma unroll
            for (int ks = 0; ks < 4; ++ks) {
                mma16816h(o[0][n0], pf[0][ks], vb0[ks]);
                mma16816h(o[1][n0], pf[1][ks], vb0[ks]);
                mma16816h(o[0][n1], pf[0][ks], vb1[ks]);
                mma16816h(o[1][n1], pf[1][ks], vb1[ks]);
            }
        }
        __syncthreads();
    }

    // ---- epilogue: normalize, write ctx fp16 [token][512] ----
    const int b = bh >> 3, h = bh & 7;
#pragma unroll
    for (int mi = 0; mi < 2; ++mi) {
        const float inv0 = 1.f / lrow[mi][0], inv1 = 1.f / lrow[mi][2];
        const int s0 = q0 + wid * 32 + mi * 16 + qr;
#pragma unroll
        for (int n = 0; n < 8; ++n) {
            const int d = h * DK + n * 8 + kkb;
            const size_t i0 = ((size_t)(b * SEQ) + s0) * D_MODEL + d;
            const size_t i1 = i0 + (size_t)8 * D_MODEL;
            *(uint32_t*)&cf[i0] = packh2(o[mi][n][0] * inv0, o[mi][n][1] * inv0);
            *(uint32_t*)&cf[i1] = packh2(o[mi][n][2] * inv1, o[mi][n][3] * inv1);
        }
    }
}

// ---------------------------------------------------------------------------
// Launch
// ---------------------------------------------------------------------------
extern "C" void kernel_launch(void* const* d_in, const int* in_sizes, int n_in,
                              void* d_out, int out_size)
{
    (void)in_sizes; (void)n_in; (void)out_size;

    const float* x  = (const float*)d_in[0];
    const float* Wq = (const float*)d_in[1];
    const float* bq = (const float*)d_in[2];
    const float* Wk = (const float*)d_in[3];
    const float* bk = (const float*)d_in[4];
    const float* Wv = (const float*)d_in[5];
    const float* bv = (const float*)d_in[6];
    const float* Wo = (const float*)d_in[7];
    const float* bo = (const float*)d_in[8];
    float* out = (float*)d_out;

    __half *xf, *wf, *qf, *kf, *vf, *cf;
    cudaGetSymbolAddress((void**)&xf, g_xf);
    cudaGetSymbolAddress((void**)&wf, g_wf);
    cudaGetSymbolAddress((void**)&qf, g_qf);
    cudaGetSymbolAddress((void**)&kf, g_kf);
    cudaGetSymbolAddress((void**)&vf, g_vf);
    cudaGetSymbolAddress((void**)&cf, g_cf);

    static bool attr_done = false;
    if (!attr_done) {
        cudaFuncSetAttribute(gemm_qkv_kernel,   cudaFuncAttributeMaxDynamicSharedMemorySize, H_SMEM_BYTES);
        cudaFuncSetAttribute(gemm_out_kernel,   cudaFuncAttributeMaxDynamicSharedMemorySize, H_SMEM_BYTES);
        cudaFuncSetAttribute(flash_hmma_kernel, cudaFuncAttributeMaxDynamicSharedMemorySize, FL_SMEM_BYTES);
        attr_done = true;
    }

    // 1) prep
    W4 ws; ws.w[0] = Wq; ws.w[1] = Wk; ws.w[2] = Wv; ws.w[3] = Wo;
    dim3 pblk(32, 8), pgrd(16, 16, 12);
    prep_kernel<<<pgrd, pblk>>>(ws, x, wf, xf);

    // 2) fused QKV projection
    dim3 gqkv(12, MTOK / 128);
    gemm_qkv_kernel<<<gqkv, 256, H_SMEM_BYTES>>>(xf, wf, bq, bk, bv, qf, kf, vf);

    // 3) flash attention
    dim3 gattn(SEQ / 128, NBH);
    flash_hmma_kernel<<<gattn, 128, FL_SMEM_BYTES>>>(qf, kf, vf, cf);

    // 4) output projection
    dim3 gout(D_MODEL / 128, MTOK / 128);
    gemm_out_kernel<<<gout, 256, H_SMEM_BYTES>>>(cf, wf + 3 * WSZ, bo, out);
}

// round 15
// speedup vs baseline: 1.0165x; 1.0165x over previous
#include <cuda_runtime.h>
#include <cuda_bf16.h>
#include <cuda_fp16.h>
#include <math_constants.h>
#include <cstdint>

// Problem constants
#define D_MODEL 512
#define NHEADS  8
#define DK      64
#define BATCH   2
#define SEQ     2048
#define MTOK    (BATCH * SEQ)   // 4096
#define NBH     (BATCH * NHEADS)
#define WSZ     (D_MODEL * D_MODEL)

#define LOG2E 1.44269504088896f

// ---------------------------------------------------------------------------
// Scratch (device globals) — all fp16
// ---------------------------------------------------------------------------
__device__ __half g_xf[MTOK * D_MODEL];       // x fp16
__device__ __half g_wf[4][WSZ];               // Wq,Wk,Wv,Wo transposed fp16
__device__ __half g_qf[NBH * SEQ * DK];       // Q fp16 (pre-scaled log2e/8)
__device__ __half g_kf[NBH * SEQ * DK];       // K fp16
__device__ __half g_vf[NBH * DK * SEQ];       // V^T fp16
__device__ __half g_cf[MTOK * D_MODEL];       // ctx fp16

// ---------------------------------------------------------------------------
// Helpers
// ---------------------------------------------------------------------------
__device__ __forceinline__ uint32_t smem_u32(const void* p) {
    uint32_t a;
    asm("{ .reg .u64 t; cvta.to.shared.u64 t, %1; cvt.u32.u64 %0, t; }"
        : "=r"(a) : "l"(p));
    return a;
}
__device__ __forceinline__ void cp16(uint32_t dst, const void* src) {
    asm volatile("cp.async.cg.shared.global [%0], [%1], 16;" :: "r"(dst), "l"(src));
}
__device__ __forceinline__ void mma16816h(float* c, const uint32_t* a, const uint32_t* b) {
    asm volatile("mma.sync.aligned.m16n8k16.row.col.f32.f16.f16.f32 "
        "{%0,%1,%2,%3}, {%4,%5,%6,%7}, {%8,%9}, {%0,%1,%2,%3};"
        : "+f"(c[0]), "+f"(c[1]), "+f"(c[2]), "+f"(c[3])
        : "r"(a[0]), "r"(a[1]), "r"(a[2]), "r"(a[3]), "r"(b[0]), "r"(b[1]));
}
__device__ __forceinline__ void ldsm_x4(uint32_t& r0, uint32_t& r1, uint32_t& r2,
                                        uint32_t& r3, uint32_t addr) {
    asm volatile("ldmatrix.sync.aligned.m8n8.x4.shared.b16 {%0,%1,%2,%3}, [%4];"
        : "=r"(r0), "=r"(r1), "=r"(r2), "=r"(r3) : "r"(addr));
}
__device__ __forceinline__ uint32_t ex2h2(uint32_t a) {
    uint32_t r;
    asm("ex2.approx.f16x2 %0, %1;" : "=r"(r) : "r"(a));
    return r;
}
__device__ __forceinline__ uint32_t packh2(float x, float y) {
    __half2 t = __floats2half2_rn(x, y);
    return *(uint32_t*)&t;
}

// ---------------------------------------------------------------------------
// Prep: weights transpose->fp16 (z<4) + x->fp16 (z>=4), one launch.
// ---------------------------------------------------------------------------
struct W4 { const float* w[4]; };

__global__ __launch_bounds__(256)
void prep_kernel(W4 ws, const float* __restrict__ x,
                 __half* __restrict__ wf, __half* __restrict__ xf)
{
    const int z = blockIdx.z;
    if (z < 4) {
        __shared__ float t[32][33];
        const float* W = ws.w[z];
        __half* dst = wf + (size_t)z * WSZ;
        const int k0 = blockIdx.x * 32, n0 = blockIdx.y * 32;
#pragma unroll
        for (int r = threadIdx.y; r < 32; r += 8)
            t[r][threadIdx.x] = W[(size_t)(k0 + r) * D_MODEL + n0 + threadIdx.x];
        __syncthreads();
#pragma unroll
        for (int r = threadIdx.y; r < 32; r += 8) {
            float v = t[threadIdx.x][r];
            dst[(size_t)(n0 + r) * D_MODEL + k0 + threadIdx.x] = __float2half_rn(v);
        }
    } else {
        const int strip = z - 4;
        const int blk   = strip * 256 + blockIdx.y * 16 + blockIdx.x;
        const int i     = blk * 256 + threadIdx.y * 32 + threadIdx.x;
        float4 v = ((const float4*)x)[i];
        uint32_t* op = (uint32_t*)xf;
        op[2 * i + 0] = packh2(v.x, v.y);
        op[2 * i + 1] = packh2(v.z, v.w);
    }
}

// ---------------------------------------------------------------------------
// fp16 HMMA GEMM core — 64x128 CTA tile, 128 thr (4 warps, warp = 64x32),
// BKC=32, 4-stage cp.async pipeline. 2 CTAs/SM.
// ---------------------------------------------------------------------------
#define HKC      32
#define HSTR     40
#define ATILE    (64 * HSTR)              // 2560 elems (A: 64 rows)
#define BTILE    (128 * HSTR)             // 5120 elems (B: 128 rows)
#define HSTAGE   (ATILE + BTILE)          // 7680 elems
#define HSTAGES  4
#define H_SMEM_BYTES (HSTAGES * HSTAGE * 2)   // 61440

// A tile: 64 rows x 32 cols = 256 16B-chunks -> 128 thr x 2 iters.
__device__ __forceinline__ void load_tileA(uint32_t sdst, const __half* src, int tid)
{
#pragma unroll
    for (int i = 0; i < 2; ++i) {
        const int idx = tid + i * 128;     // 0..255
        const int row = idx >> 2;          // 0..63
        const int c16 = idx & 3;           // 0..3
        cp16(sdst + row * (HSTR * 2) + c16 * 16,
             src + (size_t)row * D_MODEL + c16 * 8);
    }
}
// B tile: 128 rows x 32 cols = 512 16B-chunks -> 128 thr x 4 iters.
__device__ __forceinline__ void load_tileB(uint32_t sdst, const __half* src, int tid)
{
#pragma unroll
    for (int i = 0; i < 4; ++i) {
        const int idx = tid + i * 128;     // 0..511
        const int row = idx >> 2;          // 0..127
        const int c16 = idx & 3;           // 0..3
        cp16(sdst + row * (HSTR * 2) + c16 * 16,
             src + (size_t)row * D_MODEL + c16 * 8);
    }
}

__device__ __forceinline__ void gemm_mainloop_h(
    __half* sm, uint32_t smb,
    const __half* a0, const __half* bw,
    int tid, int lane, int wn, float c[4][4][4])
{
    auto sload = [&](int s, int ch) {
        const int kc = ch * HKC;
        const uint32_t sb = smb + (s * HSTAGE) * 2;
        load_tileA(sb, a0 + kc, tid);
        load_tileB(sb + ATILE * 2, bw + kc, tid);
        asm volatile("cp.async.commit_group;" ::: "memory");
    };

    const int NCHUNK = D_MODEL / HKC;  // 16
    sload(0, 0);
    sload(1, 1);
    sload(2, 2);
    const int kkb = (lane & 3) * 2;

    for (int ch = 0; ch < NCHUNK; ++ch) {
        asm volatile("cp.async.wait_group 2;" ::: "memory");
        __syncthreads();
        if (ch + 3 < NCHUNK) sload((ch + 3) & 3, ch + 3);
        else asm volatile("cp.async.commit_group;" ::: "memory");

        const int s = ch & 3;
        const __half* sA = sm + s * HSTAGE;
        const __half* sB = sA + ATILE;

#pragma unroll
        for (int k16 = 0; k16 < 2; ++k16) {
            const int kk = k16 * 16 + kkb;
            uint32_t bf[4][2];
#pragma unroll
            for (int ni = 0; ni < 4; ++ni) {
                const int rB = wn * 32 + ni * 8 + (lane >> 2);
                bf[ni][0] = *(const uint32_t*)&sB[rB * HSTR + kk];
                bf[ni][1] = *(const uint32_t*)&sB[rB * HSTR + kk + 8];
            }
#pragma unroll
            for (int mi = 0; mi < 4; ++mi) {
                const int rA = mi * 16 + (lane >> 2);
                uint32_t a[4];
                a[0] = *(const uint32_t*)&sA[(rA    ) * HSTR + kk];
                a[1] = *(const uint32_t*)&sA[(rA + 8) * HSTR + kk];
                a[2] = *(const uint32_t*)&sA[(rA    ) * HSTR + kk + 8];
                a[3] = *(const uint32_t*)&sA[(rA + 8) * HSTR + kk + 8];
#pragma unroll
                for (int ni = 0; ni < 4; ++ni)
                    mma16816h(c[mi][ni], a, bf[ni]);
            }
        }
    }
    __syncthreads();
}

// ---------------------------------------------------------------------------
// Fused QKV projection (1-pass fp16). grid (12, 64): x = which*4+ntile, y = m.
// ---------------------------------------------------------------------------
__global__ __launch_bounds__(128, 2)
void gemm_qkv_kernel(const __half* __restrict__ Xf,
                     const __half* __restrict__ Wf,
                     const float* __restrict__ bq,
                     const float* __restrict__ bk,
                     const float* __restrict__ bv,
                     __half* __restrict__ qf,
                     __half* __restrict__ kf,
                     __half* __restrict__ vf)
{
    extern __shared__ __half smh[];
    const int tid  = threadIdx.x;
    const int wn   = tid >> 5;            // warp = n-slice
    const int lane = tid & 31;
    const int which = blockIdx.x >> 2;
    const int n0   = (blockIdx.x & 3) * 128;
    const int m0   = blockIdx.y * 64;

    const float* bias = (which == 0) ? bq : (which == 1) ? bk : bv;

    float c[4][4][4] = {};
    gemm_mainloop_h(smh, smem_u32(smh),
                    Xf + (size_t)m0 * D_MODEL,
                    Wf + (size_t)which * WSZ + (size_t)n0 * D_MODEL,
                    tid, lane, wn, c);

    const float sc = (which == 0) ? (0.125f * LOG2E) : 1.0f;
#pragma unroll
    for (int mi = 0; mi < 4; ++mi) {
        const int row0 = m0 + mi * 16 + (lane >> 2);
#pragma unroll
        for (int ni = 0; ni < 4; ++ni) {
            const int col = n0 + wn * 32 + ni * 8 + (lane & 3) * 2;
            const float b0 = bias[col], b1 = bias[col + 1];
#pragma unroll
            for (int half = 0; half < 2; ++half) {
                const int m = row0 + half * 8;
                const float vx = (c[mi][ni][half * 2 + 0] + b0) * sc;
                const float vy = (c[mi][ni][half * 2 + 1] + b1) * sc;
                const int b = m >> 11, sN = m & (SEQ - 1);
                const int h = col >> 6, d = col & (DK - 1);
                if (which != 2) {
                    __half* dst = (which == 0) ? qf : kf;
                    const size_t idx = ((size_t)(b * NHEADS + h) * SEQ + sN) * DK + d;
                    *(uint32_t*)&dst[idx] = packh2(vx, vy);
                } else {
                    const size_t idx = ((size_t)(b * NHEADS + h) * DK + d) * SEQ + sN;
                    vf[idx]       = __float2half_rn(vx);
                    vf[idx + SEQ] = __float2half_rn(vy);
                }
            }
        }
    }
}

// ---------------------------------------------------------------------------
// Output projection (1-pass fp16): fp32 out + bias. grid (4, 64).
// ---------------------------------------------------------------------------
__global__ __launch_bounds__(128, 2)
void gemm_out_kernel(const __half* __restrict__ Cf,
                     const __half* __restrict__ Wo,
                     const float* __restrict__ bias,
                     float* __restrict__ outf)
{
    extern __shared__ __half smh[];
    const int tid  = threadIdx.x;
    const int wn   = tid >> 5;
    const int lane = tid & 31;
    const int n0   = blockIdx.x * 128;
    const int m0   = blockIdx.y * 64;

    float c[4][4][4] = {};
    gemm_mainloop_h(smh, smem_u32(smh),
                    Cf + (size_t)m0 * D_MODEL,
                    Wo + (size_t)n0 * D_MODEL,
                    tid, lane, wn, c);

#pragma unroll
    for (int mi = 0; mi < 4; ++mi) {
        const int row0 = m0 + mi * 16 + (lane >> 2);
#pragma unroll
        for (int ni = 0; ni < 4; ++ni) {
            const int col = n0 + wn * 32 + ni * 8 + (lane & 3) * 2;
            const float b0 = bias[col], b1 = bias[col + 1];
#pragma unroll
            for (int half = 0; half < 2; ++half) {
                const int m = row0 + half * 8;
                float2 v;
                v.x = c[mi][ni][half * 2 + 0] + b0;
                v.y = c[mi][ni][half * 2 + 1] + b1;
                *(float2*)&outf[(size_t)m * D_MODEL + col] = v;
            }
        }
    }
}

// ---------------------------------------------------------------------------
// HMMA flash attention — R12 configuration (known-good): fp16, ex2.f16x2
// softmax fused into the serial S j-loop, l via ones-MMA.
// CTA = 128 queries x one (b,h), 4 fat warps, 64-key tiles, 2 CTAs/SM.
// ---------------------------------------------------------------------------
#define KSTR   72
#define VSTR   72
#define KF_OFF 0
#define VF_OFF 4608
#define FSTG   9216
#define FL_SMEM_BYTES (2 * FSTG * 2)     // 36864 B
#define ONES_H2 0x3C003C00u

__global__ __launch_bounds__(128, 2)
void flash_hmma_kernel(const __half* __restrict__ qf,
                       const __half* __restrict__ kf,
                       const __half* __restrict__ vf,
                       __half* __restrict__ cf)
{
    extern __shared__ __half smh[];
    const int tid  = threadIdx.x;
    const int wid  = tid >> 5;
    const int lane = tid & 31;
    const int bh   = blockIdx.y;
    const int q0   = blockIdx.x * 128;
    const int kkb  = (lane & 3) * 2;
    const int qr   = lane >> 2;
    const int mrow = lane & 7;
    const int grp  = lane >> 3;

    const uint32_t smb = smem_u32(smh);
    const __half* qg = qf + ((size_t)bh * SEQ + q0) * DK;
    const __half* kg = kf + (size_t)bh * SEQ * DK;
    const __half* vg = vf + (size_t)bh * DK * SEQ;

    // ---- stage Q ----
#pragma unroll
    for (int i = 0; i < 8; ++i) {
        const int idx = tid + i * 128;
        const int row = idx >> 3;
        const int c16 = idx & 7;
        cp16(smb + (row * KSTR) * 2 + c16 * 16, qg + (size_t)row * DK + c16 * 8);
    }
    asm volatile("cp.async.commit_group;" ::: "memory");
    asm volatile("cp.async.wait_group 0;" ::: "memory");
    __syncthreads();

    uint32_t qfr[2][4][4];
#pragma unroll
    for (int mi = 0; mi < 2; ++mi) {
        const int rA = wid * 32 + mi * 16 + qr;
#pragma unroll
        for (int ks = 0; ks < 4; ++ks) {
            const int base = rA * KSTR + kkb + 16 * ks;
            qfr[mi][ks][0] = *(const uint32_t*)&smh[base];
            qfr[mi][ks][1] = *(const uint32_t*)&smh[base + 8 * KSTR];
            qfr[mi][ks][2] = *(const uint32_t*)&smh[base + 8];
            qfr[mi][ks][3] = *(const uint32_t*)&smh[base + 8 * KSTR + 8];
        }
    }
    __syncthreads();

    auto load_stage = [&](int st, int t) {
        const __half* ks = kg + (size_t)t * 64 * DK;
        const __half* vs = vg + (size_t)t * 64;
        const uint32_t sb = smb + st * FSTG * 2;
#pragma unroll
        for (int i = 0; i < 4; ++i) {
            const int idx = tid + i * 128;
            const int row = idx >> 3;
            const int c16 = idx & 7;
            cp16(sb + (KF_OFF + row * KSTR) * 2 + c16 * 16, ks + (size_t)row * DK + c16 * 8);
            cp16(sb + (VF_OFF + row * VSTR) * 2 + c16 * 16, vs + (size_t)row * SEQ + c16 * 8);
        }
        asm volatile("cp.async.commit_group;" ::: "memory");
    };

    float lrow[2][4] = {};
    float o[2][8][4] = {};
    const uint32_t onesf[2] = {ONES_H2, ONES_H2};

    const int NT = SEQ / 64;
    load_stage(0, 0);

    for (int t = 0; t < NT; ++t) {
        if (t + 1 < NT) {
            load_stage((t + 1) & 1, t + 1);
            asm volatile("cp.async.wait_group 1;" ::: "memory");
        } else {
            asm volatile("cp.async.wait_group 0;" ::: "memory");
        }
        __syncthreads();

        const uint32_t stg = smb + (t & 1) * FSTG * 2;

        // ---- S + softmax fused per j: 8 MMAs then 4 pack + 4 ex2 ----
        uint32_t pf[2][4][4];
#pragma unroll
        for (int j = 0; j < 8; ++j) {
            const uint32_t ka = stg + ((KF_OFF + (j * 8 + mrow) * KSTR + grp * 8) * 2);
            uint32_t kb[4][2];
            ldsm_x4(kb[0][0], kb[0][1], kb[1][0], kb[1][1], ka);
            ldsm_x4(kb[2][0], kb[2][1], kb[3][0], kb[3][1], ka + 64);

            float s0[4] = {0.f, 0.f, 0.f, 0.f};
            float s1[4] = {0.f, 0.f, 0.f, 0.f};
#pragma unroll
            for (int ks = 0; ks < 4; ++ks) {
                mma16816h(s0, qfr[0][ks], kb[ks]);
                mma16816h(s1, qfr[1][ks], kb[ks]);
            }
            const int kblk = j >> 1;
            const int roff = (j & 1) * 2;
            pf[0][kblk][roff + 0] = ex2h2(packh2(s0[0], s0[1]));
            pf[0][kblk][roff + 1] = ex2h2(packh2(s0[2], s0[3]));
            pf[1][kblk][roff + 0] = ex2h2(packh2(s1[0], s1[1]));
            pf[1][kblk][roff + 1] = ex2h2(packh2(s1[2], s1[3]));
        }

        // ---- l += P @ ones ----
#pragma unroll
        for (int ks = 0; ks < 4; ++ks) {
#pragma unroll
            for (int mi = 0; mi < 2; ++mi)
                mma16816h(lrow[mi], pf[mi][ks], onesf);
        }

        // ---- O += P @ V ----
#pragma unroll
        for (int n = 0; n < 8; ++n) {
            const uint32_t va = stg + ((VF_OFF + (n * 8 + mrow) * VSTR + grp * 8) * 2);
            uint32_t vb[4][2];
            ldsm_x4(vb[0][0], vb[0][1], vb[1][0], vb[1][1], va);
            ldsm_x4(vb[2][0], vb[2][1], vb[3][0], vb[3][1], va + 64);
#pragma unroll
            for (int ks = 0; ks < 4; ++ks) {
#pragma unroll
                for (int mi = 0; mi < 2; ++mi)
                    mma16816h(o[mi][n], pf[mi][ks], vb[ks]);
            }
        }
        __syncthreads();
    }

    // ---- epilogue ----
    const int b = bh >> 3, h = bh & 7;
#pragma unroll
    for (int mi = 0; mi < 2; ++mi) {
        const float inv0 = 1.f / lrow[mi][0], inv1 = 1.f / lrow[mi][2];
        const int s0 = q0 + wid * 32 + mi * 16 + qr;
#pragma unroll
        for (int n = 0; n < 8; ++n) {
            const int d = h * DK + n * 8 + kkb;
            const size_t i0 = ((size_t)(b * SEQ) + s0) * D_MODEL + d;
            const size_t i1 = i0 + (size_t)8 * D_MODEL;
            *(uint32_t*)&cf[i0] = packh2(o[mi][n][0] * inv0, o[mi][n][1] * inv0);
            *(uint32_t*)&cf[i1] = packh2(o[mi][n][2] * inv1, o[mi][n][3] * inv1);
        }
    }
}

// ---------------------------------------------------------------------------
// Launch
// ---------------------------------------------------------------------------
extern "C" void kernel_launch(void* const* d_in, const int* in_sizes, int n_in,
                              void* d_out, int out_size)
{
    (void)in_sizes; (void)n_in; (void)out_size;

    const float* x  = (const float*)d_in[0];
    const float* Wq = (const float*)d_in[1];
    const float* bq = (const float*)d_in[2];
    const float* Wk = (const float*)d_in[3];
    const float* bk = (const float*)d_in[4];
    const float* Wv = (const float*)d_in[5];
    const float* bv = (const float*)d_in[6];
    const float* Wo = (const float*)d_in[7];
    const float* bo = (const float*)d_in[8];
    float* out = (float*)d_out;

    __half *xf, *wf, *qf, *kf, *vf, *cf;
    cudaGetSymbolAddress((void**)&xf, g_xf);
    cudaGetSymbolAddress((void**)&wf, g_wf);
    cudaGetSymbolAddress((void**)&qf, g_qf);
    cudaGetSymbolAddress((void**)&kf, g_kf);
    cudaGetSymbolAddress((void**)&vf, g_vf);
    cudaGetSymbolAddress((void**)&cf, g_cf);

    static bool attr_done = false;
    if (!attr_done) {
        cudaFuncSetAttribute(gemm_qkv_kernel,   cudaFuncAttributeMaxDynamicSharedMemorySize, H_SMEM_BYTES);
        cudaFuncSetAttribute(gemm_out_kernel,   cudaFuncAttributeMaxDynamicSharedMemorySize, H_SMEM_BYTES);
        cudaFuncSetAttribute(flash_hmma_kernel, cudaFuncAttributeMaxDynamicSharedMemorySize, FL_SMEM_BYTES);
        attr_done = true;
    }

    // 1) prep
    W4 ws; ws.w[0] = Wq; ws.w[1] = Wk; ws.w[2] = Wv; ws.w[3] = Wo;
    dim3 pblk(32, 8), pgrd(16, 16, 12);
    prep_kernel<<<pgrd, pblk>>>(ws, x, wf, xf);

    // 2) fused QKV projection — 64x128 tiles, 768 CTAs
    dim3 gqkv(12, MTOK / 64);
    gemm_qkv_kernel<<<gqkv, 128, H_SMEM_BYTES>>>(xf, wf, bq, bk, bv, qf, kf, vf);

    // 3) flash attention (R12 inner loop)
    dim3 gattn(SEQ / 128, NBH);
    flash_hmma_kernel<<<gattn, 128, FL_SMEM_BYTES>>>(qf, kf, vf, cf);

    // 4) output projection — 64x128 tiles, 256 CTAs
    dim3 gout(D_MODEL / 128, MTOK / 64);
    gemm_out_kernel<<<gout, 128, H_SMEM_BYTES>>>(cf, wf + 3 * WSZ, bo, out);
}

// round 16
// speedup vs baseline: 1.0331x; 1.0164x over previous
#include <cuda_runtime.h>
#include <cuda_bf16.h>
#include <cuda_fp16.h>
#include <math_constants.h>
#include <cstdint>

// Problem constants
#define D_MODEL 512
#define NHEADS  8
#define DK      64
#define BATCH   2
#define SEQ     2048
#define MTOK    (BATCH * SEQ)   // 4096
#define NBH     (BATCH * NHEADS)
#define WSZ     (D_MODEL * D_MODEL)

#define LOG2E 1.44269504088896f

// ---------------------------------------------------------------------------
// Scratch (device globals) — all fp16
// ---------------------------------------------------------------------------
__device__ __half g_xf[MTOK * D_MODEL];       // x fp16
__device__ __half g_wf[4][WSZ];               // Wq,Wk,Wv,Wo transposed fp16
__device__ __half g_qf[NBH * SEQ * DK];       // Q fp16 (pre-scaled log2e/8)
__device__ __half g_kf[NBH * SEQ * DK];       // K fp16
__device__ __half g_vf[NBH * DK * SEQ];       // V^T fp16
__device__ __half g_cf[MTOK * D_MODEL];       // ctx fp16

// ---------------------------------------------------------------------------
// Helpers
// ---------------------------------------------------------------------------
__device__ __forceinline__ uint32_t smem_u32(const void* p) {
    uint32_t a;
    asm("{ .reg .u64 t; cvta.to.shared.u64 t, %1; cvt.u32.u64 %0, t; }"
        : "=r"(a) : "l"(p));
    return a;
}
__device__ __forceinline__ void cp16(uint32_t dst, const void* src) {
    asm volatile("cp.async.cg.shared.global [%0], [%1], 16;" :: "r"(dst), "l"(src));
}
__device__ __forceinline__ void mma16816h(float* c, const uint32_t* a, const uint32_t* b) {
    asm volatile("mma.sync.aligned.m16n8k16.row.col.f32.f16.f16.f32 "
        "{%0,%1,%2,%3}, {%4,%5,%6,%7}, {%8,%9}, {%0,%1,%2,%3};"
        : "+f"(c[0]), "+f"(c[1]), "+f"(c[2]), "+f"(c[3])
        : "r"(a[0]), "r"(a[1]), "r"(a[2]), "r"(a[3]), "r"(b[0]), "r"(b[1]));
}
__device__ __forceinline__ void ldsm_x4(uint32_t& r0, uint32_t& r1, uint32_t& r2,
                                        uint32_t& r3, uint32_t addr) {
    asm volatile("ldmatrix.sync.aligned.m8n8.x4.shared.b16 {%0,%1,%2,%3}, [%4];"
        : "=r"(r0), "=r"(r1), "=r"(r2), "=r"(r3) : "r"(addr));
}
__device__ __forceinline__ uint32_t ex2h2(uint32_t a) {
    uint32_t r;
    asm("ex2.approx.f16x2 %0, %1;" : "=r"(r) : "r"(a));
    return r;
}
__device__ __forceinline__ uint32_t packh2(float x, float y) {
    __half2 t = __floats2half2_rn(x, y);
    return *(uint32_t*)&t;
}

// ---------------------------------------------------------------------------
// Prep: weights transpose->fp16 (z<4) + x->fp16 (z>=4), one launch.
// ---------------------------------------------------------------------------
struct W4 { const float* w[4]; };

__global__ __launch_bounds__(256)
void prep_kernel(W4 ws, const float* __restrict__ x,
                 __half* __restrict__ wf, __half* __restrict__ xf)
{
    const int z = blockIdx.z;
    if (z < 4) {
        __shared__ float t[32][33];
        const float* W = ws.w[z];
        __half* dst = wf + (size_t)z * WSZ;
        const int k0 = blockIdx.x * 32, n0 = blockIdx.y * 32;
#pragma unroll
        for (int r = threadIdx.y; r < 32; r += 8)
            t[r][threadIdx.x] = W[(size_t)(k0 + r) * D_MODEL + n0 + threadIdx.x];
        __syncthreads();
#pragma unroll
        for (int r = threadIdx.y; r < 32; r += 8) {
            float v = t[threadIdx.x][r];
            dst[(size_t)(n0 + r) * D_MODEL + k0 + threadIdx.x] = __float2half_rn(v);
        }
    } else {
        const int strip = z - 4;
        const int blk   = strip * 256 + blockIdx.y * 16 + blockIdx.x;
        const int i     = blk * 256 + threadIdx.y * 32 + threadIdx.x;
        float4 v = ((const float4*)x)[i];
        uint32_t* op = (uint32_t*)xf;
        op[2 * i + 0] = packh2(v.x, v.y);
        op[2 * i + 1] = packh2(v.z, v.w);
    }
}

// ===========================================================================
// QKV GEMM (R12 config): 128x128 tile, 256 thr (8 warps 2x4), BKC=32,
// 2-stage pipeline. High B-reuse shape (12 n-tiles share weight traffic).
// ===========================================================================
#define QKC    32
#define QSTR   40
#define QTILE  (128 * QSTR)
#define Q_SMEM_BYTES (2 * 2 * QTILE * 2)  // 40960

__device__ __forceinline__ void load_tile_q(uint32_t sdst, const __half* src, int tid)
{
#pragma unroll
    for (int i = 0; i < 2; ++i) {
        const int idx = tid + i * 256;
        const int row = idx >> 2;
        const int c16 = idx & 3;
        cp16(sdst + row * (QSTR * 2) + c16 * 16,
             src + (size_t)row * D_MODEL + c16 * 8);
    }
}

__device__ __forceinline__ void gemm_mainloop_q(
    __half* sm, uint32_t smb,
    const __half* a0, const __half* bw,
    int tid, int lane, int wm, int wn, float c[4][4][4])
{
    auto sload = [&](int s, int ch) {
        const int kc = ch * QKC;
        const uint32_t sb = smb + (s * 2 * QTILE) * 2;
        load_tile_q(sb, a0 + kc, tid);
        load_tile_q(sb + QTILE * 2, bw + kc, tid);
        asm volatile("cp.async.commit_group;" ::: "memory");
    };

    const int NCHUNK = D_MODEL / QKC;  // 16
    sload(0, 0);
    const int kkb = (lane & 3) * 2;

    for (int ch = 0; ch < NCHUNK; ++ch) {
        asm volatile("cp.async.wait_group 0;" ::: "memory");
        __syncthreads();
        if (ch + 1 < NCHUNK) sload((ch + 1) & 1, ch + 1);

        const int s = ch & 1;
        const __half* sA = sm + s * 2 * QTILE;
        const __half* sB = sA + QTILE;

#pragma unroll
        for (int k16 = 0; k16 < 2; ++k16) {
            const int kk = k16 * 16 + kkb;
            uint32_t bf[4][2];
#pragma unroll
            for (int ni = 0; ni < 4; ++ni) {
                const int rB = wn * 32 + ni * 8 + (lane >> 2);
                bf[ni][0] = *(const uint32_t*)&sB[rB * QSTR + kk];
                bf[ni][1] = *(const uint32_t*)&sB[rB * QSTR + kk + 8];
            }
#pragma unroll
            for (int mi = 0; mi < 4; ++mi) {
                const int rA = wm * 64 + mi * 16 + (lane >> 2);
                uint32_t a[4];
                a[0] = *(const uint32_t*)&sA[(rA    ) * QSTR + kk];
                a[1] = *(const uint32_t*)&sA[(rA + 8) * QSTR + kk];
                a[2] = *(const uint32_t*)&sA[(rA    ) * QSTR + kk + 8];
                a[3] = *(const uint32_t*)&sA[(rA + 8) * QSTR + kk + 8];
#pragma unroll
                for (int ni = 0; ni < 4; ++ni)
                    mma16816h(c[mi][ni], a, bf[ni]);
            }
        }
        __syncthreads();
    }
}

__global__ __launch_bounds__(256, 2)
void gemm_qkv_kernel(const __half* __restrict__ Xf,
                     const __half* __restrict__ Wf,
                     const float* __restrict__ bq,
                     const float* __restrict__ bk,
                     const float* __restrict__ bv,
                     __half* __restrict__ qf,
                     __half* __restrict__ kf,
                     __half* __restrict__ vf)
{
    extern __shared__ __half smh[];
    const int tid  = threadIdx.x;
    const int wid  = tid >> 5;
    const int lane = tid & 31;
    const int wm   = wid >> 2;
    const int wn   = wid & 3;
    const int which = blockIdx.x >> 2;
    const int n0   = (blockIdx.x & 3) * 128;
    const int m0   = blockIdx.y * 128;

    const float* bias = (which == 0) ? bq : (which == 1) ? bk : bv;

    float c[4][4][4] = {};
    gemm_mainloop_q(smh, smem_u32(smh),
                    Xf + (size_t)m0 * D_MODEL,
                    Wf + (size_t)which * WSZ + (size_t)n0 * D_MODEL,
                    tid, lane, wm, wn, c);

    const float sc = (which == 0) ? (0.125f * LOG2E) : 1.0f;
#pragma unroll
    for (int mi = 0; mi < 4; ++mi) {
        const int row0 = m0 + wm * 64 + mi * 16 + (lane >> 2);
#pragma unroll
        for (int ni = 0; ni < 4; ++ni) {
            const int col = n0 + wn * 32 + ni * 8 + (lane & 3) * 2;
            const float b0 = bias[col], b1 = bias[col + 1];
#pragma unroll
            for (int half = 0; half < 2; ++half) {
                const int m = row0 + half * 8;
                const float vx = (c[mi][ni][half * 2 + 0] + b0) * sc;
                const float vy = (c[mi][ni][half * 2 + 1] + b1) * sc;
                const int b = m >> 11, sN = m & (SEQ - 1);
                const int h = col >> 6, d = col & (DK - 1);
                if (which != 2) {
                    __half* dst = (which == 0) ? qf : kf;
                    const size_t idx = ((size_t)(b * NHEADS + h) * SEQ + sN) * DK + d;
                    *(uint32_t*)&dst[idx] = packh2(vx, vy);
                } else {
                    const size_t idx = ((size_t)(b * NHEADS + h) * DK + d) * SEQ + sN;
                    vf[idx]       = __float2half_rn(vx);
                    vf[idx + SEQ] = __float2half_rn(vy);
                }
            }
        }
    }
}

// ===========================================================================
// Output projection (R15 config): 64x128 tile, 128 thr (4 warps), BKC=32,
// 4-stage pipeline, 256 CTAs. Low-reuse shape wins here (B L2-resident).
// ===========================================================================
#define OSTR     40
#define OATILE   (64 * OSTR)
#define OBTILE   (128 * OSTR)
#define OSTAGE   (OATILE + OBTILE)
#define O_SMEM_BYTES (4 * OSTAGE * 2)     // 61440

__device__ __forceinline__ void load_tileA_o(uint32_t sdst, const __half* src, int tid)
{
#pragma unroll
    for (int i = 0; i < 2; ++i) {
        const int idx = tid + i * 128;     // 0..255
        const int row = idx >> 2;
        const int c16 = idx & 3;
        cp16(sdst + row * (OSTR * 2) + c16 * 16,
             src + (size_t)row * D_MODEL + c16 * 8);
    }
}
__device__ __forceinline__ void load_tileB_o(uint32_t sdst, const __half* src, int tid)
{
#pragma unroll
    for (int i = 0; i < 4; ++i) {
        const int idx = tid + i * 128;     // 0..511
        const int row = idx >> 2;
        const int c16 = idx & 3;
        cp16(sdst + row * (OSTR * 2) + c16 * 16,
             src + (size_t)row * D_MODEL + c16 * 8);
    }
}

__global__ __launch_bounds__(128, 2)
void gemm_out_kernel(const __half* __restrict__ Cf,
                     const __half* __restrict__ Wo,
                     const float* __restrict__ bias,
                     float* __restrict__ outf)
{
    extern __shared__ __half smh[];
    const int tid  = threadIdx.x;
    const int wn   = tid >> 5;
    const int lane = tid & 31;
    const int n0   = blockIdx.x * 128;
    const int m0   = blockIdx.y * 64;

    const __half* a0 = Cf + (size_t)m0 * D_MODEL;
    const __half* bw = Wo + (size_t)n0 * D_MODEL;
    const uint32_t smb = smem_u32(smh);

    auto sload = [&](int s, int ch) {
        const int kc = ch * 32;
        const uint32_t sb = smb + (s * OSTAGE) * 2;
        load_tileA_o(sb, a0 + kc, tid);
        load_tileB_o(sb + OATILE * 2, bw + kc, tid);
        asm volatile("cp.async.commit_group;" ::: "memory");
    };

    float c[4][4][4] = {};
    const int NCHUNK = D_MODEL / 32;   // 16
    sload(0, 0);
    sload(1, 1);
    sload(2, 2);
    const int kkb = (lane & 3) * 2;

    for (int ch = 0; ch < NCHUNK; ++ch) {
        asm volatile("cp.async.wait_group 2;" ::: "memory");
        __syncthreads();
        if (ch + 3 < NCHUNK) sload((ch + 3) & 3, ch + 3);
        else asm volatile("cp.async.commit_group;" ::: "memory");

        const int s = ch & 3;
        const __half* sA = smh + s * OSTAGE;
        const __half* sB = sA + OATILE;

#pragma unroll
        for (int k16 = 0; k16 < 2; ++k16) {
            const int kk = k16 * 16 + kkb;
            uint32_t bf[4][2];
#pragma unroll
            for (int ni = 0; ni < 4; ++ni) {
                const int rB = wn * 32 + ni * 8 + (lane >> 2);
                bf[ni][0] = *(const uint32_t*)&sB[rB * OSTR + kk];
                bf[ni][1] = *(const uint32_t*)&sB[rB * OSTR + kk + 8];
            }
#pragma unroll
            for (int mi = 0; mi < 4; ++mi) {
                const int rA = mi * 16 + (lane >> 2);
                uint32_t a[4];
                a[0] = *(const uint32_t*)&sA[(rA    ) * OSTR + kk];
                a[1] = *(const uint32_t*)&sA[(rA + 8) * OSTR + kk];
                a[2] = *(const uint32_t*)&sA[(rA    ) * OSTR + kk + 8];
                a[3] = *(const uint32_t*)&sA[(rA + 8) * OSTR + kk + 8];
#pragma unroll
                for (int ni = 0; ni < 4; ++ni)
                    mma16816h(c[mi][ni], a, bf[ni]);
            }
        }
    }
    __syncthreads();

#pragma unroll
    for (int mi = 0; mi < 4; ++mi) {
        const int row0 = m0 + mi * 16 + (lane >> 2);
#pragma unroll
        for (int ni = 0; ni < 4; ++ni) {
            const int col = n0 + wn * 32 + ni * 8 + (lane & 3) * 2;
            const float b0 = bias[col], b1 = bias[col + 1];
#pragma unroll
            for (int half = 0; half < 2; ++half) {
                const int m = row0 + half * 8;
                float2 v;
                v.x = c[mi][ni][half * 2 + 0] + b0;
                v.y = c[mi][ni][half * 2 + 1] + b1;
                *(float2*)&outf[(size_t)m * D_MODEL + col] = v;
            }
        }
    }
}

// ===========================================================================
// HMMA flash attention — R12 configuration (known-good).
// ===========================================================================
#define KSTR   72
#define VSTR   72
#define KF_OFF 0
#define VF_OFF 4608
#define FSTG   9216
#define FL_SMEM_BYTES (2 * FSTG * 2)     // 36864 B
#define ONES_H2 0x3C003C00u

__global__ __launch_bounds__(128, 2)
void flash_hmma_kernel(const __half* __restrict__ qf,
                       const __half* __restrict__ kf,
                       const __half* __restrict__ vf,
                       __half* __restrict__ cf)
{
    extern __shared__ __half smh[];
    const int tid  = threadIdx.x;
    const int wid  = tid >> 5;
    const int lane = tid & 31;
    const int bh   = blockIdx.y;
    const int q0   = blockIdx.x * 128;
    const int kkb  = (lane & 3) * 2;
    const int qr   = lane >> 2;
    const int mrow = lane & 7;
    const int grp  = lane >> 3;

    const uint32_t smb = smem_u32(smh);
    const __half* qg = qf + ((size_t)bh * SEQ + q0) * DK;
    const __half* kg = kf + (size_t)bh * SEQ * DK;
    const __half* vg = vf + (size_t)bh * DK * SEQ;

    // ---- stage Q ----
#pragma unroll
    for (int i = 0; i < 8; ++i) {
        const int idx = tid + i * 128;
        const int row = idx >> 3;
        const int c16 = idx & 7;
        cp16(smb + (row * KSTR) * 2 + c16 * 16, qg + (size_t)row * DK + c16 * 8);
    }
    asm volatile("cp.async.commit_group;" ::: "memory");
    asm volatile("cp.async.wait_group 0;" ::: "memory");
    __syncthreads();

    uint32_t qfr[2][4][4];
#pragma unroll
    for (int mi = 0; mi < 2; ++mi) {
        const int rA = wid * 32 + mi * 16 + qr;
#pragma unroll
        for (int ks = 0; ks < 4; ++ks) {
            const int base = rA * KSTR + kkb + 16 * ks;
            qfr[mi][ks][0] = *(const uint32_t*)&smh[base];
            qfr[mi][ks][1] = *(const uint32_t*)&smh[base + 8 * KSTR];
            qfr[mi][ks][2] = *(const uint32_t*)&smh[base + 8];
            qfr[mi][ks][3] = *(const uint32_t*)&smh[base + 8 * KSTR + 8];
        }
    }
    __syncthreads();

    auto load_stage = [&](int st, int t) {
        const __half* ks = kg + (size_t)t * 64 * DK;
        const __half* vs = vg + (size_t)t * 64;
        const uint32_t sb = smb + st * FSTG * 2;
#pragma unroll
        for (int i = 0; i < 4; ++i) {
            const int idx = tid + i * 128;
            const int row = idx >> 3;
            const int c16 = idx & 7;
            cp16(sb + (KF_OFF + row * KSTR) * 2 + c16 * 16, ks + (size_t)row * DK + c16 * 8);
            cp16(sb + (VF_OFF + row * VSTR) * 2 + c16 * 16, vs + (size_t)row * SEQ + c16 * 8);
        }
        asm volatile("cp.async.commit_group;" ::: "memory");
    };

    float lrow[2][4] = {};
    float o[2][8][4] = {};
    const uint32_t onesf[2] = {ONES_H2, ONES_H2};

    const int NT = SEQ / 64;
    load_stage(0, 0);

    for (int t = 0; t < NT; ++t) {
        if (t + 1 < NT) {
            load_stage((t + 1) & 1, t + 1);
            asm volatile("cp.async.wait_group 1;" ::: "memory");
        } else {
            asm volatile("cp.async.wait_group 0;" ::: "memory");
        }
        __syncthreads();

        const uint32_t stg = smb + (t & 1) * FSTG * 2;

        // ---- S + softmax fused per j ----
        uint32_t pf[2][4][4];
#pragma unroll
        for (int j = 0; j < 8; ++j) {
            const uint32_t ka = stg + ((KF_OFF + (j * 8 + mrow) * KSTR + grp * 8) * 2);
            uint32_t kb[4][2];
            ldsm_x4(kb[0][0], kb[0][1], kb[1][0], kb[1][1], ka);
            ldsm_x4(kb[2][0], kb[2][1], kb[3][0], kb[3][1], ka + 64);

            float s0[4] = {0.f, 0.f, 0.f, 0.f};
            float s1[4] = {0.f, 0.f, 0.f, 0.f};
#pragma unroll
            for (int ks = 0; ks < 4; ++ks) {
                mma16816h(s0, qfr[0][ks], kb[ks]);
                mma16816h(s1, qfr[1][ks], kb[ks]);
            }
            const int kblk = j >> 1;
            const int roff = (j & 1) * 2;
            pf[0][kblk][roff + 0] = ex2h2(packh2(s0[0], s0[1]));
            pf[0][kblk][roff + 1] = ex2h2(packh2(s0[2], s0[3]));
            pf[1][kblk][roff + 0] = ex2h2(packh2(s1[0], s1[1]));
            pf[1][kblk][roff + 1] = ex2h2(packh2(s1[2], s1[3]));
        }

        // ---- l += P @ ones ----
#pragma unroll
        for (int ks = 0; ks < 4; ++ks) {
#pragma unroll
            for (int mi = 0; mi < 2; ++mi)
                mma16816h(lrow[mi], pf[mi][ks], onesf);
        }

        // ---- O += P @ V ----
#pragma unroll
        for (int n = 0; n < 8; ++n) {
            const uint32_t va = stg + ((VF_OFF + (n * 8 + mrow) * VSTR + grp * 8) * 2);
            uint32_t vb[4][2];
            ldsm_x4(vb[0][0], vb[0][1], vb[1][0], vb[1][1], va);
            ldsm_x4(vb[2][0], vb[2][1], vb[3][0], vb[3][1], va + 64);
#pragma unroll
            for (int ks = 0; ks < 4; ++ks) {
#pragma unroll
                for (int mi = 0; mi < 2; ++mi)
                    mma16816h(o[mi][n], pf[mi][ks], vb[ks]);
            }
        }
        __syncthreads();
    }

    // ---- epilogue ----
    const int b = bh >> 3, h = bh & 7;
#pragma unroll
    for (int mi = 0; mi < 2; ++mi) {
        const float inv0 = 1.f / lrow[mi][0], inv1 = 1.f / lrow[mi][2];
        const int s0 = q0 + wid * 32 + mi * 16 + qr;
#pragma unroll
        for (int n = 0; n < 8; ++n) {
            const int d = h * DK + n * 8 + kkb;
            const size_t i0 = ((size_t)(b * SEQ) + s0) * D_MODEL + d;
            const size_t i1 = i0 + (size_t)8 * D_MODEL;
            *(uint32_t*)&cf[i0] = packh2(o[mi][n][0] * inv0, o[mi][n][1] * inv0);
            *(uint32_t*)&cf[i1] = packh2(o[mi][n][2] * inv1, o[mi][n][3] * inv1);
        }
    }
}

// ---------------------------------------------------------------------------
// Launch
// ---------------------------------------------------------------------------
extern "C" void kernel_launch(void* const* d_in, const int* in_sizes, int n_in,
                              void* d_out, int out_size)
{
    (void)in_sizes; (void)n_in; (void)out_size;

    const float* x  = (const float*)d_in[0];
    const float* Wq = (const float*)d_in[1];
    const float* bq = (const float*)d_in[2];
    const float* Wk = (const float*)d_in[3];
    const float* bk = (const float*)d_in[4];
    const float* Wv = (const float*)d_in[5];
    const float* bv = (const float*)d_in[6];
    const float* Wo = (const float*)d_in[7];
    const float* bo = (const float*)d_in[8];
    float* out = (float*)d_out;

    __half *xf, *wf, *qf, *kf, *vf, *cf;
    cudaGetSymbolAddress((void**)&xf, g_xf);
    cudaGetSymbolAddress((void**)&wf, g_wf);
    cudaGetSymbolAddress((void**)&qf, g_qf);
    cudaGetSymbolAddress((void**)&kf, g_kf);
    cudaGetSymbolAddress((void**)&vf, g_vf);
    cudaGetSymbolAddress((void**)&cf, g_cf);

    static bool attr_done = false;
    if (!attr_done) {
        cudaFuncSetAttribute(gemm_qkv_kernel,   cudaFuncAttributeMaxDynamicSharedMemorySize, Q_SMEM_BYTES);
        cudaFuncSetAttribute(gemm_out_kernel,   cudaFuncAttributeMaxDynamicSharedMemorySize, O_SMEM_BYTES);
        cudaFuncSetAttribute(flash_hmma_kernel, cudaFuncAttributeMaxDynamicSharedMemorySize, FL_SMEM_BYTES);
        attr_done = true;
    }

    // 1) prep
    W4 ws; ws.w[0] = Wq; ws.w[1] = Wk; ws.w[2] = Wv; ws.w[3] = Wo;
    dim3 pblk(32, 8), pgrd(16, 16, 12);
    prep_kernel<<<pgrd, pblk>>>(ws, x, wf, xf);

    // 2) fused QKV projection — 128x128 tiles, 384 CTAs (R12 config)
    dim3 gqkv(12, MTOK / 128);
    gemm_qkv_kernel<<<gqkv, 256, Q_SMEM_BYTES>>>(xf, wf, bq, bk, bv, qf, kf, vf);

    // 3) flash attention (R12 config)
    dim3 gattn(SEQ / 128, NBH);
    flash_hmma_kernel<<<gattn, 128, FL_SMEM_BYTES>>>(qf, kf, vf, cf);

    // 4) output projection — 64x128 tiles, 256 CTAs (R15 config)
    dim3 gout(D_MODEL / 128, MTOK / 64);
    gemm_out_kernel<<<gout, 128, O_SMEM_BYTES>>>(cf, wf + 3 * WSZ, bo, out);
}